// round 15
// baseline (speedup 1.0000x reference)
#include <cuda_runtime.h>
#include <cuda_bf16.h>
#include <cstdint>
#include <math.h>

// QuantumNet fused, round 14: zero-sync pure-LDG streaming.
// Each warp independently owns 8 consecutive rows (16KB linear).
// Warp-cooperative coalesced LDG.128 (512B/warp-instr), register weights,
// butterfly reduce (sum lands in all lanes -> lane r keeps row r),
// per-lane collapsed Clifford epilogue. No smem, no barriers, no TMA.

#define KDIM 512
#define THREADS 64              // 2 warps per CTA
#define ROWS_PER_WARP 8
#define ROWS_PER_CTA (ROWS_PER_WARP * 2)   // 16

__global__ __launch_bounds__(THREADS)
void qnet_kernel(const float* __restrict__ x,
                 const float* __restrict__ pre_w,
                 const float* __restrict__ pre_b,
                 const float* __restrict__ u3p,
                 const float* __restrict__ post_w,
                 const float* __restrict__ post_b,
                 float* __restrict__ out, int B)
{
    const int tid  = threadIdx.x;
    const int wid  = tid >> 5;
    const int lane = tid & 31;
    const int gw   = blockIdx.x * 2 + wid;      // global warp id
    const int rbase = gw * ROWS_PER_WARP;       // first row this warp owns
    if (rbase >= B) return;

    // ---- weights into registers: lane covers k = i*128 + lane*4 + m ----
    float wreg[4][4][4];   // [i][m][q]
    #pragma unroll
    for (int i = 0; i < 4; ++i)
        #pragma unroll
        for (int q = 0; q < 4; ++q) {
            float4 v = *(const float4*)(pre_w + q * KDIM + i * 128 + lane * 4);
            wreg[i][0][q] = v.x; wreg[i][1][q] = v.y;
            wreg[i][2][q] = v.z; wreg[i][3][q] = v.w;
        }

    const float4* __restrict__ x4 = (const float4*)x;

    // lanes 0..7 will each retain the 4 pre-activation sums of "their" row
    float s0 = 0.f, s1 = 0.f, s2 = 0.f, s3 = 0.f;

    #pragma unroll
    for (int p = 0; p < 4; ++p) {               // 4 row-pairs
        const int r0 = rbase + 2 * p;
        const int r1 = r0 + 1;
        const bool v0 = (r0 < B), v1 = (r1 < B);

        float4 u0[4], u1[4];
        #pragma unroll
        for (int i = 0; i < 4; ++i)
            u0[i] = v0 ? x4[(size_t)r0 * 128 + i * 32 + lane]
                       : make_float4(0.f, 0.f, 0.f, 0.f);
        #pragma unroll
        for (int i = 0; i < 4; ++i)
            u1[i] = v1 ? x4[(size_t)r1 * 128 + i * 32 + lane]
                       : make_float4(0.f, 0.f, 0.f, 0.f);

        float a0 = 0.f, a1 = 0.f, a2 = 0.f, a3 = 0.f;
        float b0 = 0.f, b1 = 0.f, b2 = 0.f, b3 = 0.f;
        #pragma unroll
        for (int i = 0; i < 4; ++i) {
            float4 xa = u0[i], xb = u1[i];
            a0 = fmaf(xa.x, wreg[i][0][0], a0); a1 = fmaf(xa.x, wreg[i][0][1], a1);
            a2 = fmaf(xa.x, wreg[i][0][2], a2); a3 = fmaf(xa.x, wreg[i][0][3], a3);
            b0 = fmaf(xb.x, wreg[i][0][0], b0); b1 = fmaf(xb.x, wreg[i][0][1], b1);
            b2 = fmaf(xb.x, wreg[i][0][2], b2); b3 = fmaf(xb.x, wreg[i][0][3], b3);
            a0 = fmaf(xa.y, wreg[i][1][0], a0); a1 = fmaf(xa.y, wreg[i][1][1], a1);
            a2 = fmaf(xa.y, wreg[i][1][2], a2); a3 = fmaf(xa.y, wreg[i][1][3], a3);
            b0 = fmaf(xb.y, wreg[i][1][0], b0); b1 = fmaf(xb.y, wreg[i][1][1], b1);
            b2 = fmaf(xb.y, wreg[i][1][2], b2); b3 = fmaf(xb.y, wreg[i][1][3], b3);
            a0 = fmaf(xa.z, wreg[i][2][0], a0); a1 = fmaf(xa.z, wreg[i][2][1], a1);
            a2 = fmaf(xa.z, wreg[i][2][2], a2); a3 = fmaf(xa.z, wreg[i][2][3], a3);
            b0 = fmaf(xb.z, wreg[i][2][0], b0); b1 = fmaf(xb.z, wreg[i][2][1], b1);
            b2 = fmaf(xb.z, wreg[i][2][2], b2); b3 = fmaf(xb.z, wreg[i][2][3], b3);
            a0 = fmaf(xa.w, wreg[i][3][0], a0); a1 = fmaf(xa.w, wreg[i][3][1], a1);
            a2 = fmaf(xa.w, wreg[i][3][2], a2); a3 = fmaf(xa.w, wreg[i][3][3], a3);
            b0 = fmaf(xb.w, wreg[i][3][0], b0); b1 = fmaf(xb.w, wreg[i][3][1], b1);
            b2 = fmaf(xb.w, wreg[i][3][2], b2); b3 = fmaf(xb.w, wreg[i][3][3], b3);
        }

        // butterfly: after this every lane holds the warp-wide sums
        #pragma unroll
        for (int off = 16; off >= 1; off >>= 1) {
            a0 += __shfl_xor_sync(0xFFFFFFFFu, a0, off);
            a1 += __shfl_xor_sync(0xFFFFFFFFu, a1, off);
            a2 += __shfl_xor_sync(0xFFFFFFFFu, a2, off);
            a3 += __shfl_xor_sync(0xFFFFFFFFu, a3, off);
            b0 += __shfl_xor_sync(0xFFFFFFFFu, b0, off);
            b1 += __shfl_xor_sync(0xFFFFFFFFu, b1, off);
            b2 += __shfl_xor_sync(0xFFFFFFFFu, b2, off);
            b3 += __shfl_xor_sync(0xFFFFFFFFu, b3, off);
        }
        // lane (2p) keeps row r0, lane (2p+1) keeps row r1
        if (lane == 2 * p)     { s0 = a0; s1 = a1; s2 = a2; s3 = a3; }
        if (lane == 2 * p + 1) { s0 = b0; s1 = b1; s2 = b2; s3 = b3; }
    }

    // ---- epilogue: lanes 0..7 each finish their own row ----
    if (lane >= ROWS_PER_WARP) return;
    const int row = rbase + lane;
    if (row >= B) return;

    const float HALF_PI = 1.5707963267948966f;
    float z[4], xq[4], yq[4];
    float pre[4] = { s0 + pre_b[0], s1 + pre_b[1],
                     s2 + pre_b[2], s3 + pre_b[3] };
    #pragma unroll
    for (int q = 0; q < 4; ++q) {
        float t  = tanhf(pre[q] * 0.1f) * HALF_PI;
        float u  = t * t;
        float cr = rsqrtf(fmaf(t, t, 1.f));
        float cz = rsqrtf(fmaf(u, u, 1.f));
        z[q]  = -t * cr;
        xq[q] = cr * cz;
        yq[q] = xq[q] * u;
    }

    float cg[4], mx[4], my[4];
    #pragma unroll
    for (int q = 0; q < 4; ++q) {
        float th = u3p[q * 3 + 0];
        float la = u3p[q * 3 + 2];
        float st_, ct_, sl_, cl_;
        __sincosf(th, &st_, &ct_);
        __sincosf(la, &sl_, &cl_);
        cg[q] = ct_;
        mx[q] = -st_ * cl_;
        my[q] =  st_ * sl_;
    }

    // Clifford-conjugated Pauli strings:
    // Z~: Z0Z1Z2 | Z0Z1Z2Z3 | Z0Z3 | Z2Z3
    // X~: X0X1X2X3 | X0X2X3 | X0X1 | X1X2
    // Y~: -Y0Y1Y2X3 | -Y0Z1Y2Y3 | Y0X1Z3 | X1Y2Z3
    float z01 = z[0] * z[1];
    float E0 = cg[0] * (z01 * z[2])
             + mx[0] * (xq[0] * xq[1] * xq[2] * xq[3])
             - my[0] * (yq[0] * yq[1] * yq[2] * xq[3]);
    float E1 = cg[1] * (z01 * z[2] * z[3])
             + mx[1] * (xq[0] * xq[2] * xq[3])
             - my[1] * (yq[0] * z[1] * yq[2] * yq[3]);
    float E2 = cg[2] * (z[0] * z[3])
             + mx[2] * (xq[0] * xq[1])
             + my[2] * (yq[0] * xq[1] * z[3]);
    float E3 = cg[3] * (z[2] * z[3])
             + mx[3] * (xq[1] * xq[2])
             + my[3] * (xq[1] * yq[2] * z[3]);

    float o0 = post_b[0], o1 = post_b[1];
    o0 = fmaf(post_w[0], E0, o0); o1 = fmaf(post_w[4], E0, o1);
    o0 = fmaf(post_w[1], E1, o0); o1 = fmaf(post_w[5], E1, o1);
    o0 = fmaf(post_w[2], E2, o0); o1 = fmaf(post_w[6], E2, o1);
    o0 = fmaf(post_w[3], E3, o0); o1 = fmaf(post_w[7], E3, o1);

    float2 res; res.x = o0; res.y = o1;
    ((float2*)out)[row] = res;
}

extern "C" void kernel_launch(void* const* d_in, const int* in_sizes, int n_in,
                              void* d_out, int out_size) {
    const float* x      = (const float*)d_in[0];
    const float* pre_w  = (const float*)d_in[1];
    const float* pre_b  = (const float*)d_in[2];
    const float* u3p    = (const float*)d_in[3];
    const float* post_w = (const float*)d_in[4];
    const float* post_b = (const float*)d_in[5];
    float* out = (float*)d_out;

    int B = in_sizes[0] / KDIM;
    int grid = (B + ROWS_PER_CTA - 1) / ROWS_PER_CTA;
    qnet_kernel<<<grid, THREADS>>>(x, pre_w, pre_b, u3p, post_w, post_b, out, B);
}

// round 16
// speedup vs baseline: 1.3567x; 1.3567x over previous
#include <cuda_runtime.h>
#include <cuda_bf16.h>
#include <cstdint>
#include <math.h>

// QuantumNet fused, round 15: R12 structure with 16KB bulk chunks.
// chunk = 8 rows (16KB contiguous) via one cp.async.bulk, depth-2 ring
// (32KB smem -> ~7 CTAs/SM resident). Per chunk each of 4 warps computes
// 2 rows (dual accumulators + one butterfly). Register weights, collapsed
// Clifford epilogue.

#define KDIM 512
#define ROWS 32                 // rows per CTA
#define THREADS 128             // 4 warps
#define CHUNK_ROWS 8
#define NCHUNKS (ROWS / CHUNK_ROWS)    // 4
#define NSTAGES 2
#define CHUNK_FLOATS (CHUNK_ROWS * KDIM)   // 4096 (16KB)

__device__ __forceinline__ unsigned smem_u32(const void* p) {
    return (unsigned)__cvta_generic_to_shared(p);
}
__device__ __forceinline__ void mbar_init(unsigned mbar, unsigned count) {
    asm volatile("mbarrier.init.shared.b64 [%0], %1;" :: "r"(mbar), "r"(count) : "memory");
}
__device__ __forceinline__ void mbar_expect_tx(unsigned mbar, unsigned bytes) {
    asm volatile("mbarrier.arrive.expect_tx.shared.b64 _, [%0], %1;"
                 :: "r"(mbar), "r"(bytes) : "memory");
}
__device__ __forceinline__ void bulk_ld(unsigned dst_smem, const void* src,
                                        unsigned bytes, unsigned mbar) {
    asm volatile(
        "cp.async.bulk.shared::cluster.global.mbarrier::complete_tx::bytes "
        "[%0], [%1], %2, [%3];"
        :: "r"(dst_smem), "l"(src), "r"(bytes), "r"(mbar) : "memory");
}
__device__ __forceinline__ void mbar_wait(unsigned mbar, unsigned parity) {
    asm volatile(
        "{\n\t"
        ".reg .pred P1;\n\t"
        "WAIT_LOOP_%=:\n\t"
        "mbarrier.try_wait.parity.acquire.cta.shared::cta.b64 P1, [%0], %1, 0x989680;\n\t"
        "@P1 bra.uni WAIT_DONE_%=;\n\t"
        "bra.uni WAIT_LOOP_%=;\n\t"
        "WAIT_DONE_%=:\n\t"
        "}"
        :: "r"(mbar), "r"(parity) : "memory");
}

__global__ __launch_bounds__(THREADS)
void qnet_kernel(const float* __restrict__ x,
                 const float* __restrict__ pre_w,
                 const float* __restrict__ pre_b,
                 const float* __restrict__ u3p,
                 const float* __restrict__ post_w,
                 const float* __restrict__ post_b,
                 float* __restrict__ out, int B)
{
    __shared__ float xs[NSTAGES][CHUNK_FLOATS];          // 2 x 16 KB
    __shared__ float red[ROWS * 4];                      // 512 B partials
    __shared__ __align__(8) unsigned long long mbar[NSTAGES];

    const int tid  = threadIdx.x;
    const int wid  = tid >> 5;         // warp 0..3
    const int lane = tid & 31;
    const int row0 = blockIdx.x * ROWS;
    const int nrows = (B - row0 < ROWS) ? (B - row0) : ROWS;

    // ---- weights into registers: lane covers k = i*128 + lane*4 + m ----
    float wreg[4][4][4];   // [i][m][q]
    #pragma unroll
    for (int i = 0; i < 4; ++i)
        #pragma unroll
        for (int q = 0; q < 4; ++q) {
            float4 v = *(const float4*)(pre_w + q * KDIM + i * 128 + lane * 4);
            wreg[i][0][q] = v.x; wreg[i][1][q] = v.y;
            wreg[i][2][q] = v.z; wreg[i][3][q] = v.w;
        }

    unsigned mb[NSTAGES], xsa[NSTAGES];
    #pragma unroll
    for (int s = 0; s < NSTAGES; ++s) {
        mb[s]  = smem_u32(&mbar[s]);
        xsa[s] = smem_u32(&xs[s][0]);
    }

    if (tid == 0) {
        #pragma unroll
        for (int s = 0; s < NSTAGES; ++s) mbar_init(mb[s], 1);
        asm volatile("fence.proxy.async.shared::cta;" ::: "memory");
    }
    __syncthreads();

    // one 16KB linear bulk copy per chunk
    auto issue_chunk = [&](int c, int s) {
        if (tid == 0) {
            int cr = nrows - c * CHUNK_ROWS;
            if (cr > CHUNK_ROWS) cr = CHUNK_ROWS;
            unsigned bytes = (cr > 0) ? (unsigned)(cr * KDIM * 4) : 0u;
            mbar_expect_tx(mb[s], bytes);
            if (bytes)
                bulk_ld(xsa[s], x + ((size_t)row0 + c * CHUNK_ROWS) * KDIM,
                        bytes, mb[s]);
        }
    };

    issue_chunk(0, 0);
    issue_chunk(1, 1);

    #pragma unroll
    for (int c = 0; c < NCHUNKS; ++c) {
        const int s = c & 1;
        mbar_wait(mb[s], (c >> 1) & 1);

        // warp wid handles chunk-local rows wid*2 and wid*2+1
        const int lr0 = c * CHUNK_ROWS + wid * 2;     // CTA-local rows
        const int lr1 = lr0 + 1;
        const bool v0 = (lr0 < nrows), v1 = (lr1 < nrows);
        if (v0 | v1) {
            const float4* xa4 = (const float4*)&xs[s][(wid * 2 + 0) * KDIM];
            const float4* xb4 = (const float4*)&xs[s][(wid * 2 + 1) * KDIM];
            float a0 = 0.f, a1 = 0.f, a2 = 0.f, a3 = 0.f;
            float b0 = 0.f, b1 = 0.f, b2 = 0.f, b3 = 0.f;
            #pragma unroll
            for (int i = 0; i < 4; ++i) {
                float4 xa = v0 ? xa4[i * 32 + lane] : make_float4(0.f,0.f,0.f,0.f);
                float4 xb = v1 ? xb4[i * 32 + lane] : make_float4(0.f,0.f,0.f,0.f);
                a0 = fmaf(xa.x, wreg[i][0][0], a0); a1 = fmaf(xa.x, wreg[i][0][1], a1);
                a2 = fmaf(xa.x, wreg[i][0][2], a2); a3 = fmaf(xa.x, wreg[i][0][3], a3);
                b0 = fmaf(xb.x, wreg[i][0][0], b0); b1 = fmaf(xb.x, wreg[i][0][1], b1);
                b2 = fmaf(xb.x, wreg[i][0][2], b2); b3 = fmaf(xb.x, wreg[i][0][3], b3);
                a0 = fmaf(xa.y, wreg[i][1][0], a0); a1 = fmaf(xa.y, wreg[i][1][1], a1);
                a2 = fmaf(xa.y, wreg[i][1][2], a2); a3 = fmaf(xa.y, wreg[i][1][3], a3);
                b0 = fmaf(xb.y, wreg[i][1][0], b0); b1 = fmaf(xb.y, wreg[i][1][1], b1);
                b2 = fmaf(xb.y, wreg[i][1][2], b2); b3 = fmaf(xb.y, wreg[i][1][3], b3);
                a0 = fmaf(xa.z, wreg[i][2][0], a0); a1 = fmaf(xa.z, wreg[i][2][1], a1);
                a2 = fmaf(xa.z, wreg[i][2][2], a2); a3 = fmaf(xa.z, wreg[i][2][3], a3);
                b0 = fmaf(xb.z, wreg[i][2][0], b0); b1 = fmaf(xb.z, wreg[i][2][1], b1);
                b2 = fmaf(xb.z, wreg[i][2][2], b2); b3 = fmaf(xb.z, wreg[i][2][3], b3);
                a0 = fmaf(xa.w, wreg[i][3][0], a0); a1 = fmaf(xa.w, wreg[i][3][1], a1);
                a2 = fmaf(xa.w, wreg[i][3][2], a2); a3 = fmaf(xa.w, wreg[i][3][3], a3);
                b0 = fmaf(xb.w, wreg[i][3][0], b0); b1 = fmaf(xb.w, wreg[i][3][1], b1);
                b2 = fmaf(xb.w, wreg[i][3][2], b2); b3 = fmaf(xb.w, wreg[i][3][3], b3);
            }
            #pragma unroll
            for (int off = 16; off >= 1; off >>= 1) {
                a0 += __shfl_xor_sync(0xFFFFFFFFu, a0, off);
                a1 += __shfl_xor_sync(0xFFFFFFFFu, a1, off);
                a2 += __shfl_xor_sync(0xFFFFFFFFu, a2, off);
                a3 += __shfl_xor_sync(0xFFFFFFFFu, a3, off);
                b0 += __shfl_xor_sync(0xFFFFFFFFu, b0, off);
                b1 += __shfl_xor_sync(0xFFFFFFFFu, b1, off);
                b2 += __shfl_xor_sync(0xFFFFFFFFu, b2, off);
                b3 += __shfl_xor_sync(0xFFFFFFFFu, b3, off);
            }
            if (lane == 0 && v0) {
                float4 v; v.x = a0; v.y = a1; v.z = a2; v.w = a3;
                *(float4*)&red[lr0 * 4] = v;
            }
            if (lane == 1 && v1) {
                float4 v; v.x = b0; v.y = b1; v.z = b2; v.w = b3;
                *(float4*)&red[lr1 * 4] = v;
            }
        }
        __syncthreads();   // stage consumed + red writes ordered

        if (c + NSTAGES < NCHUNKS)
            issue_chunk(c + NSTAGES, s);
    }

    // ---- epilogue: one thread per row ----
    if (tid >= nrows) return;
    float4 pv = *(const float4*)&red[tid * 4];
    const int row = row0 + tid;

    const float HALF_PI = 1.5707963267948966f;
    float z[4], xq[4], yq[4];
    float pre[4] = { pv.x + pre_b[0], pv.y + pre_b[1],
                     pv.z + pre_b[2], pv.w + pre_b[3] };
    #pragma unroll
    for (int q = 0; q < 4; ++q) {
        float t  = tanhf(pre[q] * 0.1f) * HALF_PI;
        float u  = t * t;
        float cr = rsqrtf(fmaf(t, t, 1.f));
        float cz = rsqrtf(fmaf(u, u, 1.f));
        z[q]  = -t * cr;
        xq[q] = cr * cz;
        yq[q] = xq[q] * u;
    }

    float cg[4], mx[4], my[4];
    #pragma unroll
    for (int q = 0; q < 4; ++q) {
        float th = u3p[q * 3 + 0];
        float la = u3p[q * 3 + 2];
        float st_, ct_, sl_, cl_;
        __sincosf(th, &st_, &ct_);
        __sincosf(la, &sl_, &cl_);
        cg[q] = ct_;
        mx[q] = -st_ * cl_;
        my[q] =  st_ * sl_;
    }

    // Clifford-conjugated Pauli strings:
    // Z~: Z0Z1Z2 | Z0Z1Z2Z3 | Z0Z3 | Z2Z3
    // X~: X0X1X2X3 | X0X2X3 | X0X1 | X1X2
    // Y~: -Y0Y1Y2X3 | -Y0Z1Y2Y3 | Y0X1Z3 | X1Y2Z3
    float z01 = z[0] * z[1];
    float E0 = cg[0] * (z01 * z[2])
             + mx[0] * (xq[0] * xq[1] * xq[2] * xq[3])
             - my[0] * (yq[0] * yq[1] * yq[2] * xq[3]);
    float E1 = cg[1] * (z01 * z[2] * z[3])
             + mx[1] * (xq[0] * xq[2] * xq[3])
             - my[1] * (yq[0] * z[1] * yq[2] * yq[3]);
    float E2 = cg[2] * (z[0] * z[3])
             + mx[2] * (xq[0] * xq[1])
             + my[2] * (yq[0] * xq[1] * z[3]);
    float E3 = cg[3] * (z[2] * z[3])
             + mx[3] * (xq[1] * xq[2])
             + my[3] * (xq[1] * yq[2] * z[3]);

    float o0 = post_b[0], o1 = post_b[1];
    o0 = fmaf(post_w[0], E0, o0); o1 = fmaf(post_w[4], E0, o1);
    o0 = fmaf(post_w[1], E1, o0); o1 = fmaf(post_w[5], E1, o1);
    o0 = fmaf(post_w[2], E2, o0); o1 = fmaf(post_w[6], E2, o1);
    o0 = fmaf(post_w[3], E3, o0); o1 = fmaf(post_w[7], E3, o1);

    float2 res; res.x = o0; res.y = o1;
    ((float2*)out)[row] = res;
}

extern "C" void kernel_launch(void* const* d_in, const int* in_sizes, int n_in,
                              void* d_out, int out_size) {
    const float* x      = (const float*)d_in[0];
    const float* pre_w  = (const float*)d_in[1];
    const float* pre_b  = (const float*)d_in[2];
    const float* u3p    = (const float*)d_in[3];
    const float* post_w = (const float*)d_in[4];
    const float* post_b = (const float*)d_in[5];
    float* out = (float*)d_out;

    int B = in_sizes[0] / KDIM;
    int grid = (B + ROWS - 1) / ROWS;
    qnet_kernel<<<grid, THREADS>>>(x, pre_w, pre_b, u3p, post_w, post_b, out, B);
}